// round 2
// baseline (speedup 1.0000x reference)
#include <cuda_runtime.h>

typedef unsigned long long u64;

// ---------------------------------------------------------------------------
// Problem constants
//   x:        [32, 64, 128, 128] f32
//   attention:[32, 4]            f32
//   weight:   [4, 64, 64, 3, 3]  f32   (k, oc, ic, ky, kx)
//   bias_p:   [4, 64]            f32
//   out:      [32, 64, 128, 128] f32
// out[b,o,y,x] = sum_{i,ky,kx} w_mix[b,o,i,ky,kx] * x[b,i,y+ky-1,x+kx-1] + b_mix[b,o]
// w_mix[b] = sum_k attention[b,k] * weight[k]
// ---------------------------------------------------------------------------

#define NB   32
#define NC   64
#define HW   128
#define NK   4
#define KK   9          // 3x3
#define WSZ  (NC*NC*KK) // 36864 per bank / per sample

// Scratch: mixed weights in layout [b][ic][kk][oc] (oc fastest -> f32x2 pairs),
// and mixed bias [b][oc]. __device__ globals (allocation-free).
__device__ __align__(16) float g_wmix[NB * WSZ];   // 4.7 MB
__device__ __align__(16) float g_bmix[NB * NC];

// ---------------- f32x2 helpers (Blackwell packed fp32) --------------------
__device__ __forceinline__ u64 dup2(float v) {
    u64 r;
    asm("mov.b64 %0, {%1, %1};" : "=l"(r) : "f"(v));
    return r;
}
__device__ __forceinline__ void fma2(u64 &d, u64 a, u64 b) {
    asm("fma.rn.f32x2 %0, %1, %2, %0;" : "+l"(d) : "l"(a), "l"(b));
}
__device__ __forceinline__ float2 unpack2(u64 v) {
    float2 f;
    asm("mov.b64 {%0, %1}, %2;" : "=f"(f.x), "=f"(f.y) : "l"(v));
    return f;
}

// ---------------------------------------------------------------------------
// Kernel 1: mix the 4-kernel bank per sample.
//   g_wmix[b][(ic*9+kk)*64 + oc] = sum_k att[b,k] * weight[k][oc][ic][kk]
// Reads coalesced over the weight banks (i2 is contiguous per bank),
// writes scattered once (tiny, L2-absorbed).
// ---------------------------------------------------------------------------
__global__ void mix_kernel(const float* __restrict__ att,
                           const float* __restrict__ w,
                           const float* __restrict__ bias_p) {
    const int b = blockIdx.x;
    const float a0 = att[b * NK + 0];
    const float a1 = att[b * NK + 1];
    const float a2 = att[b * NK + 2];
    const float a3 = att[b * NK + 3];

    for (int i2 = threadIdx.x; i2 < WSZ; i2 += blockDim.x) {
        // i2 enumerates (oc, ic, kk) in bank layout
        const int kk = i2 % KK;
        const int ic = (i2 / KK) & (NC - 1);
        const int oc = i2 / (KK * NC);
        const float s = a0 * w[i2]
                      + a1 * w[i2 + WSZ]
                      + a2 * w[i2 + 2 * WSZ]
                      + a3 * w[i2 + 3 * WSZ];
        g_wmix[b * WSZ + (ic * KK + kk) * NC + oc] = s;
    }
    if (threadIdx.x < NC) {
        const int oc = threadIdx.x;
        g_bmix[b * NC + oc] = a0 * bias_p[oc]
                            + a1 * bias_p[NC + oc]
                            + a2 * bias_p[2 * NC + oc]
                            + a3 * bias_p[3 * NC + oc];
    }
}

// ---------------------------------------------------------------------------
// Kernel 2: direct conv, f32x2-packed over output-channel pairs.
//   Block: one (sample b, oc group of 8, 32x32 spatial tile).
//   256 threads = 32 (x) x 8 (row-group). Thread micro-tile:
//   4 consecutive rows x 1 column x 8 oc  -> 16 f32x2 accumulators.
//   Inner: acc[pr][jp] += dup(x_val) * wpair[jp]  (wpair = 2 adjacent oc)
// ---------------------------------------------------------------------------
#define OCT   8           // oc per block
#define TILE  32          // spatial tile edge
#define ICC   4           // input channels per smem chunk
#define SIN_W 36          // padded smem row width (cols 0..33 valid)

__global__ __launch_bounds__(256)
void conv_kernel(const float* __restrict__ x, float* __restrict__ out) {
    __shared__ __align__(16) float sW[NC * KK * OCT];        // 18 KB: [ic][kk][oc8]
    __shared__ __align__(16) float sIn[ICC][TILE + 2][SIN_W]; // ~19.6 KB

    const int tid = threadIdx.x;
    const int tx  = tid & 31;        // output column within tile
    const int ty  = tid >> 5;        // row group 0..7 (4 rows each)
    const int b   = blockIdx.z;
    const int ocg = blockIdx.y;      // 0..7
    const int tile = blockIdx.x;     // 0..15
    const int ty0 = (tile >> 2) * TILE;
    const int tx0 = (tile & 3) * TILE;

    // Load this block's mixed-weight slice: sW[(ic*9+kk)*8 + oc]
    {
        const float* wsrc = g_wmix + b * WSZ + ocg * OCT;
        for (int i = tid; i < NC * KK * OCT; i += 256) {
            const int oc   = i & (OCT - 1);
            const int ickk = i >> 3;          // ic*9+kk
            sW[i] = wsrc[ickk * NC + oc];
        }
    }

    u64 acc[4][4];
    #pragma unroll
    for (int p = 0; p < 4; p++)
        #pragma unroll
        for (int j = 0; j < 4; j++) acc[p][j] = 0ull;

    const float* xb = x + (size_t)b * NC * HW * HW;

    for (int icb = 0; icb < NC / ICC; icb++) {
        // ---- stage input chunk (ICC channels, 34x34 halo tile, zero-padded)
        for (int i = tid; i < ICC * 34 * 34; i += 256) {
            const int col = i % 34;
            const int row = (i / 34) % 34;
            const int ic  = i / (34 * 34);
            const int gy  = ty0 + row - 1;
            const int gx  = tx0 + col - 1;
            float v = 0.0f;
            if (gy >= 0 && gy < HW && gx >= 0 && gx < HW)
                v = xb[((icb * ICC + ic) * HW + gy) * HW + gx];
            sIn[ic][row][col] = v;
        }
        __syncthreads();

        // ---- compute
        #pragma unroll
        for (int ic = 0; ic < ICC; ic++) {
            const float* wrow = &sW[(icb * ICC + ic) * KK * OCT];
            #pragma unroll
            for (int ky = 0; ky < 3; ky++) {
                // input values: rows 4*ty+pr+ky, cols tx..tx+2
                float av[4][3];
                #pragma unroll
                for (int pr = 0; pr < 4; pr++) {
                    const float* rp = &sIn[ic][4 * ty + pr + ky][tx];
                    av[pr][0] = rp[0];
                    av[pr][1] = rp[1];
                    av[pr][2] = rp[2];
                }
                #pragma unroll
                for (int kx = 0; kx < 3; kx++) {
                    const float* wp = &wrow[(ky * 3 + kx) * OCT];
                    const u64 w0 = *(const u64*)(wp + 0);
                    const u64 w1 = *(const u64*)(wp + 2);
                    const u64 w2 = *(const u64*)(wp + 4);
                    const u64 w3 = *(const u64*)(wp + 6);
                    #pragma unroll
                    for (int pr = 0; pr < 4; pr++) {
                        const u64 d = dup2(av[pr][kx]);
                        fma2(acc[pr][0], d, w0);
                        fma2(acc[pr][1], d, w1);
                        fma2(acc[pr][2], d, w2);
                        fma2(acc[pr][3], d, w3);
                    }
                }
            }
        }
        __syncthreads();   // before next chunk overwrites sIn
    }

    // ---- epilogue: add mixed bias, store (coalesced over tx)
    const u64* bm = (const u64*)(g_bmix + b * NC + ocg * OCT);
    float* ob = out + (size_t)b * NC * HW * HW + (size_t)(ocg * OCT) * HW * HW;
    #pragma unroll
    for (int j = 0; j < 4; j++) {
        const float2 bias = unpack2(bm[j]);
        #pragma unroll
        for (int pr = 0; pr < 4; pr++) {
            const float2 v = unpack2(acc[pr][j]);
            const int y  = ty0 + 4 * ty + pr;
            const int xo = tx0 + tx;
            ob[(size_t)(2 * j)     * HW * HW + y * HW + xo] = v.x + bias.x;
            ob[(size_t)(2 * j + 1) * HW * HW + y * HW + xo] = v.y + bias.y;
        }
    }
}

// ---------------------------------------------------------------------------
extern "C" void kernel_launch(void* const* d_in, const int* in_sizes, int n_in,
                              void* d_out, int out_size) {
    (void)in_sizes; (void)n_in; (void)out_size;
    const float* x      = (const float*)d_in[0];
    const float* att    = (const float*)d_in[1];
    const float* weight = (const float*)d_in[2];
    const float* bias_p = (const float*)d_in[3];
    float* out = (float*)d_out;

    mix_kernel<<<NB, 256>>>(att, weight, bias_p);

    dim3 grid(16, NC / OCT, NB);   // (spatial tiles, oc groups, batch)
    conv_kernel<<<grid, 256>>>(x, out);
}

// round 4
// speedup vs baseline: 1.0010x; 1.0010x over previous
#include <cuda_runtime.h>

typedef unsigned long long u64;

// ---------------------------------------------------------------------------
// Problem constants
//   x:        [32, 64, 128, 128] f32
//   attention:[32, 4]            f32
//   weight:   [4, 64, 64, 3, 3]  f32   (k, oc, ic, ky, kx)
//   bias_p:   [4, 64]            f32
//   out:      [32, 64, 128, 128] f32
// out[b,o,y,x] = sum_{i,ky,kx} w_mix[b,o,i,ky,kx] * x[b,i,y+ky-1,x+kx-1] + b_mix[b,o]
// w_mix[b] = sum_k attention[b,k] * weight[k]
// ---------------------------------------------------------------------------

#define NB   32
#define NC   64
#define HW   128
#define NK   4
#define KK   9          // 3x3
#define WSZ  (NC*NC*KK) // 36864 per bank / per sample

// Scratch: mixed weights in layout [b][ic][kk][oc] (oc fastest -> f32x2 pairs),
// and mixed bias [b][oc]. __device__ globals (allocation-free).
__device__ __align__(16) float g_wmix[NB * WSZ];   // 4.7 MB
__device__ __align__(16) float g_bmix[NB * NC];

// ---------------- f32x2 helpers (Blackwell packed fp32) --------------------
__device__ __forceinline__ u64 dup2(float v) {
    u64 r;
    asm("mov.b64 %0, {%1, %1};" : "=l"(r) : "f"(v));
    return r;
}
__device__ __forceinline__ void fma2(u64 &d, u64 a, u64 b) {
    asm("fma.rn.f32x2 %0, %1, %2, %0;" : "+l"(d) : "l"(a), "l"(b));
}
__device__ __forceinline__ float2 unpack2(u64 v) {
    float2 f;
    asm("mov.b64 {%0, %1}, %2;" : "=f"(f.x), "=f"(f.y) : "l"(v));
    return f;
}

// ---------------------------------------------------------------------------
// Kernel 1: mix the 4-kernel bank per sample.
//   g_wmix[b][(ic*9+kk)*64 + oc] = sum_k att[b,k] * weight[k][oc][ic][kk]
// Reads coalesced over the weight banks (i2 is contiguous per bank),
// writes scattered once (tiny, L2-absorbed).
// ---------------------------------------------------------------------------
__global__ void mix_kernel(const float* __restrict__ att,
                           const float* __restrict__ w,
                           const float* __restrict__ bias_p) {
    const int b = blockIdx.x;
    const float a0 = att[b * NK + 0];
    const float a1 = att[b * NK + 1];
    const float a2 = att[b * NK + 2];
    const float a3 = att[b * NK + 3];

    for (int i2 = threadIdx.x; i2 < WSZ; i2 += blockDim.x) {
        // i2 enumerates (oc, ic, kk) in bank layout
        const int kk = i2 % KK;
        const int ic = (i2 / KK) & (NC - 1);
        const int oc = i2 / (KK * NC);
        const float s = a0 * w[i2]
                      + a1 * w[i2 + WSZ]
                      + a2 * w[i2 + 2 * WSZ]
                      + a3 * w[i2 + 3 * WSZ];
        g_wmix[b * WSZ + (ic * KK + kk) * NC + oc] = s;
    }
    if (threadIdx.x < NC) {
        const int oc = threadIdx.x;
        g_bmix[b * NC + oc] = a0 * bias_p[oc]
                            + a1 * bias_p[NC + oc]
                            + a2 * bias_p[2 * NC + oc]
                            + a3 * bias_p[3 * NC + oc];
    }
}

// ---------------------------------------------------------------------------
// Kernel 2: direct conv, f32x2-packed over output-channel pairs.
//   Block: one (sample b, oc group of 8, 32x32 spatial tile).
//   256 threads = 32 (x) x 8 (row-group). Thread micro-tile:
//   4 consecutive rows x 1 column x 8 oc  -> 16 f32x2 accumulators.
//   Inner: acc[pr][jp] += dup(x_val) * wpair[jp]  (wpair = 2 adjacent oc)
// ---------------------------------------------------------------------------
#define OCT   8           // oc per block
#define TILE  32          // spatial tile edge
#define ICC   4           // input channels per smem chunk
#define SIN_W 36          // padded smem row width (cols 0..33 valid)

__global__ __launch_bounds__(256)
void conv_kernel(const float* __restrict__ x, float* __restrict__ out) {
    __shared__ __align__(16) float sW[NC * KK * OCT];        // 18 KB: [ic][kk][oc8]
    __shared__ __align__(16) float sIn[ICC][TILE + 2][SIN_W]; // ~19.6 KB

    const int tid = threadIdx.x;
    const int tx  = tid & 31;        // output column within tile
    const int ty  = tid >> 5;        // row group 0..7 (4 rows each)
    const int b   = blockIdx.z;
    const int ocg = blockIdx.y;      // 0..7
    const int tile = blockIdx.x;     // 0..15
    const int ty0 = (tile >> 2) * TILE;
    const int tx0 = (tile & 3) * TILE;

    // Load this block's mixed-weight slice: sW[(ic*9+kk)*8 + oc]
    {
        const float* wsrc = g_wmix + b * WSZ + ocg * OCT;
        for (int i = tid; i < NC * KK * OCT; i += 256) {
            const int oc   = i & (OCT - 1);
            const int ickk = i >> 3;          // ic*9+kk
            sW[i] = wsrc[ickk * NC + oc];
        }
    }

    u64 acc[4][4];
    #pragma unroll
    for (int p = 0; p < 4; p++)
        #pragma unroll
        for (int j = 0; j < 4; j++) acc[p][j] = 0ull;

    const float* xb = x + (size_t)b * NC * HW * HW;

    for (int icb = 0; icb < NC / ICC; icb++) {
        // ---- stage input chunk (ICC channels, 34x34 halo tile, zero-padded)
        for (int i = tid; i < ICC * 34 * 34; i += 256) {
            const int col = i % 34;
            const int row = (i / 34) % 34;
            const int ic  = i / (34 * 34);
            const int gy  = ty0 + row - 1;
            const int gx  = tx0 + col - 1;
            float v = 0.0f;
            if (gy >= 0 && gy < HW && gx >= 0 && gx < HW)
                v = xb[((icb * ICC + ic) * HW + gy) * HW + gx];
            sIn[ic][row][col] = v;
        }
        __syncthreads();

        // ---- compute
        #pragma unroll
        for (int ic = 0; ic < ICC; ic++) {
            const float* wrow = &sW[(icb * ICC + ic) * KK * OCT];
            #pragma unroll
            for (int ky = 0; ky < 3; ky++) {
                // input values: rows 4*ty+pr+ky, cols tx..tx+2
                float av[4][3];
                #pragma unroll
                for (int pr = 0; pr < 4; pr++) {
                    const float* rp = &sIn[ic][4 * ty + pr + ky][tx];
                    av[pr][0] = rp[0];
                    av[pr][1] = rp[1];
                    av[pr][2] = rp[2];
                }
                #pragma unroll
                for (int kx = 0; kx < 3; kx++) {
                    const float* wp = &wrow[(ky * 3 + kx) * OCT];
                    const u64 w0 = *(const u64*)(wp + 0);
                    const u64 w1 = *(const u64*)(wp + 2);
                    const u64 w2 = *(const u64*)(wp + 4);
                    const u64 w3 = *(const u64*)(wp + 6);
                    #pragma unroll
                    for (int pr = 0; pr < 4; pr++) {
                        const u64 d = dup2(av[pr][kx]);
                        fma2(acc[pr][0], d, w0);
                        fma2(acc[pr][1], d, w1);
                        fma2(acc[pr][2], d, w2);
                        fma2(acc[pr][3], d, w3);
                    }
                }
            }
        }
        __syncthreads();   // before next chunk overwrites sIn
    }

    // ---- epilogue: add mixed bias, store (coalesced over tx)
    const u64* bm = (const u64*)(g_bmix + b * NC + ocg * OCT);
    float* ob = out + (size_t)b * NC * HW * HW + (size_t)(ocg * OCT) * HW * HW;
    #pragma unroll
    for (int j = 0; j < 4; j++) {
        const float2 bias = unpack2(bm[j]);
        #pragma unroll
        for (int pr = 0; pr < 4; pr++) {
            const float2 v = unpack2(acc[pr][j]);
            const int y  = ty0 + 4 * ty + pr;
            const int xo = tx0 + tx;
            ob[(size_t)(2 * j)     * HW * HW + y * HW + xo] = v.x + bias.x;
            ob[(size_t)(2 * j + 1) * HW * HW + y * HW + xo] = v.y + bias.y;
        }
    }
}

// ---------------------------------------------------------------------------
extern "C" void kernel_launch(void* const* d_in, const int* in_sizes, int n_in,
                              void* d_out, int out_size) {
    (void)in_sizes; (void)n_in; (void)out_size;
    const float* x      = (const float*)d_in[0];
    const float* att    = (const float*)d_in[1];
    const float* weight = (const float*)d_in[2];
    const float* bias_p = (const float*)d_in[3];
    float* out = (float*)d_out;

    mix_kernel<<<NB, 256>>>(att, weight, bias_p);

    dim3 grid(16, NC / OCT, NB);   // (spatial tiles, oc groups, batch)
    conv_kernel<<<grid, 256>>>(x, out);
}